// round 16
// baseline (speedup 1.0000x reference)
#include <cuda_runtime.h>
#include <math.h>
#include <float.h>
#include <stdint.h>

// Problem constants (fixed by the reference)
#define B_IMG  32
#define D_DIM  256
#define HW_SZ  4096     // H*W = 64*64
#define K_CB   512
#define NCLS   10
#define NSHR   10

// Tiling (champion shape; stride bumped to 260 for 16B-aligned code rows)
#define TP     256      // pixels per block
#define KT     56       // padded candidate codes (8 ty-groups x 7)
#define CBS2   260      // smem codebook row stride (divisible by 4 -> LDS.128)
#define CHROWS 32       // d-rows staged per chunk
#define NCHNK  (D_DIM / CHROWS)
#define NTHR   256

#define F32_INF __int_as_float(0x7f800000)

struct ClassRanges { int lo[NCLS]; int cnt[NCLS]; };

typedef unsigned long long ull;

// ---- packed f32x2 helpers (Blackwell): exact per-lane IEEE fp32 semantics --
__device__ __forceinline__ ull pack2(float x) {
    unsigned int b = __float_as_uint(x);
    ull r;
    asm("mov.b64 %0, {%1, %1};" : "=l"(r) : "r"(b));
    return r;
}
__device__ __forceinline__ ull pairb(float lo, float hi) {
    ull r;
    asm("mov.b64 %0, {%1, %2};" : "=l"(r)
        : "r"(__float_as_uint(lo)), "r"(__float_as_uint(hi)));
    return r;
}
__device__ __forceinline__ void fma2(ull& d, ull a, ull b) {
    asm("fma.rn.f32x2 %0, %1, %2, %0;" : "+l"(d) : "l"(a), "l"(b));
}
__device__ __forceinline__ ull mul2(ull a, ull b) {
    ull r;
    asm("mul.rn.f32x2 %0, %1, %2;" : "=l"(r) : "l"(a), "l"(b));
    return r;
}
__device__ __forceinline__ void add2(ull& d, ull a) {
    asm("add.rn.f32x2 %0, %0, %1;" : "+l"(d) : "l"(a));
}
__device__ __forceinline__ float2 unpack2(ull v) {
    unsigned int lo, hi;
    asm("mov.b64 {%0, %1}, %2;" : "=r"(lo), "=r"(hi) : "l"(v));
    return make_float2(__uint_as_float(lo), __uint_as_float(hi));
}

// ----------------------------------------------------------------------------
// One block: image b, 256 contiguous pixels. Candidate codes = contiguous
// codebook slice [lo, lo+cnt), row-major in smem (stride 260 -> rows 16B
// aligned). Warp ty owns codes [7ty, 7ty+6]; lane tx owns pixels
// {4tx..4tx+3} and {128+4tx..+3} (validated mapping, R4).
//
// Argmin path (bit-exact vs reference, validated rel_err=0.0 R2..R14):
//   A   = in_sqr  : per-pixel sequential ascending sum of fl(x_d*x_d)
//                   (fused into the GEMM loop, ty==0, packed mul2/add2 — R9)
//   g_k = x . c_k : sequential ascending fused-FMA chain (one register lane)
//   d_k = fl( fl(A + p_k) - 2*g_k );  argmin, first-min tie-break.
//
// Output path (validated R15, rel_err ~2.2e-5 << 1e-3): BOTH outputs = codes.
// ----------------------------------------------------------------------------
__global__ void __launch_bounds__(NTHR, 2)
vq_kernel(const float* __restrict__ z, const float* __restrict__ cb,
          const int* __restrict__ labels, float* __restrict__ out,
          ClassRanges cr)
{
    extern __shared__ float smem[];
    float* cb_s = smem;                       // [KT][CBS2]  56*260*4 = 58.2 KB
    float* p_s  = cb_s + KT * CBS2;           // [64]  cb_sqr (+inf pads)
    float* A_s  = p_s + 64;                   // [256] in_sqr per pixel
    float* x_s  = A_s + 256;                  // [CHROWS][256], reused later

    const int tid = threadIdx.x;
    const int tx  = tid & 31;                 // pixel-group lane
    const int ty  = tid >> 5;                 // code group (0..7)
    const int b   = blockIdx.y;
    const int hw0 = blockIdx.x * TP;

    const int label = labels[b];
    const int lo    = cr.lo[label];
    const int cnt   = cr.cnt[label];          // 50 or 51

    // ---- load codebook slice (padded rows = 0), float4-vectorized ----
    for (int i = tid; i < KT * (D_DIM / 4); i += NTHR) {
        const int kk = i >> 6;                // 64 float4 per row
        const int d4 = (i & 63) << 2;
        float4 v = make_float4(0.f, 0.f, 0.f, 0.f);
        if (kk < cnt) v = *(const float4*)(cb + (size_t)(lo + kk) * D_DIM + d4);
        *(float4*)&cb_s[kk * CBS2 + d4] = v;
    }
    __syncthreads();

    // ---- cb_sqr per row (conflict-free: bank = 4kk + tx mod 32) ----
    #pragma unroll
    for (int j = 0; j < 7; ++j) {
        const int kk = ty * 7 + j;
        float s = 0.0f;
        #pragma unroll
        for (int d = tx; d < D_DIM; d += 32) {
            const float v = cb_s[kk * CBS2 + d];
            s = __fadd_rn(s, __fmul_rn(v, v));
        }
        #pragma unroll
        for (int o = 16; o > 0; o >>= 1)
            s = __fadd_rn(s, __shfl_xor_sync(0xffffffffu, s, o));
        if (tx == 0)
            p_s[kk] = (kk < cnt) ? s : F32_INF;
    }

    // ---- main pass over 8 chunks of 32 d-rows ----
    ull acc[7][4];                            // g chains: 7 codes x 4 px-pairs
    #pragma unroll
    for (int j = 0; j < 7; ++j)
        #pragma unroll
        for (int r = 0; r < 4; ++r) acc[j][r] = 0ULL;
    ull asq[4];                               // in_sqr pairs (ty==0 only)
    #pragma unroll
    for (int r = 0; r < 4; ++r) asq[r] = 0ULL;

    const float* xbase = z + (size_t)b * D_DIM * HW_SZ + hw0;
    const bool grp0 = (ty == 0);              // warp-uniform

    for (int ch = 0; ch < NCHNK; ++ch) {
        const int dc0 = ch * CHROWS;
        const float* xs = xbase + (size_t)dc0 * HW_SZ;
        __syncthreads();                       // protect x_s reuse
        // stage x chunk [32 d][256 px] (float4, coalesced; 8 per thread)
        for (int i = tid; i < CHROWS * 64; i += NTHR) {
            const int row = i >> 6;
            const int c4  = (i & 63) << 2;
            *(float4*)&x_s[(row << 8) + c4] =
                *(const float4*)(xs + (size_t)row * HW_SZ + c4);
        }
        __syncthreads();

        // GEMM + fused in_sqr: 4 d per iteration; codes via LDS.128
        #pragma unroll 1
        for (int dd = 0; dd < CHROWS; dd += 4) {
            float4 cp4[7];
            #pragma unroll
            for (int j = 0; j < 7; ++j)
                cp4[j] = *(const float4*)&cb_s[(ty * 7 + j) * CBS2 + dc0 + dd];

            #pragma unroll
            for (int h = 0; h < 4; ++h) {     // the four d's
                const float* row = x_s + ((dd + h) << 8);
                const float4 a = *(const float4*)(row + (tx << 2));
                const float4 c = *(const float4*)(row + 128 + (tx << 2));
                ull xp[4];
                xp[0] = pairb(a.x, a.y);  xp[1] = pairb(a.z, a.w);
                xp[2] = pairb(c.x, c.y);  xp[3] = pairb(c.z, c.w);

                if (grp0) {                    // bit-exact per-pixel chains
                    add2(asq[0], mul2(xp[0], xp[0]));
                    add2(asq[1], mul2(xp[1], xp[1]));
                    add2(asq[2], mul2(xp[2], xp[2]));
                    add2(asq[3], mul2(xp[3], xp[3]));
                }

                #pragma unroll
                for (int j = 0; j < 7; ++j) {
                    const float cv = (h == 0) ? cp4[j].x :
                                     (h == 1) ? cp4[j].y :
                                     (h == 2) ? cp4[j].z : cp4[j].w;
                    const ull c2 = pack2(cv);
                    #pragma unroll
                    for (int r = 0; r < 4; ++r) fma2(acc[j][r], xp[r], c2);
                }
            }
        }
    }
    if (grp0) {
        *(float2*)&A_s[(tx << 2)]       = unpack2(asq[0]);
        *(float2*)&A_s[(tx << 2) + 2]   = unpack2(asq[1]);
        *(float2*)&A_s[128 + (tx << 2)]     = unpack2(asq[2]);
        *(float2*)&A_s[128 + (tx << 2) + 2] = unpack2(asq[3]);
    }
    __syncthreads();

    // ---- distances d = fl(fl(A + p) - 2g); per-thread first-min argmin ----
    float* rs   = x_s;                        // [8][256] best distance
    int*   ri   = (int*)(x_s + 8 * 256);      // [8][256] slice indices
    int*   best = (int*)(x_s + 16 * 256);     // [256]

    #pragma unroll
    for (int r = 0; r < 4; ++r) {
        // slot r covers pixel pair p0 = 4tx + 2*(r&1) + 128*(r>>1)
        const int p0 = (tx << 2) + ((r & 1) << 1) + ((r >> 1) << 7);
        const float2 Av = *(const float2*)&A_s[p0];
        float bd0 = F32_INF, bd1 = F32_INF;
        int   bi0 = 0,       bi1 = 0;
        #pragma unroll
        for (int j = 0; j < 7; ++j) {
            const int kk = ty * 7 + j;
            const float p = p_s[kk];
            const float2 g = unpack2(acc[j][r]);
            const float d0 = __fadd_rn(__fadd_rn(Av.x, p), -(2.0f * g.x));
            const float d1 = __fadd_rn(__fadd_rn(Av.y, p), -(2.0f * g.y));
            if (d0 < bd0) { bd0 = d0; bi0 = kk; }  // strict < keeps lowest idx
            if (d1 < bd1) { bd1 = d1; bi1 = kk; }
        }
        rs[ty * 256 + p0]     = bd0;  ri[ty * 256 + p0]     = bi0;
        rs[ty * 256 + p0 + 1] = bd1;  ri[ty * 256 + p0 + 1] = bi1;
    }
    __syncthreads();

    {
        float bd = rs[tid];
        int   bi = ri[tid];
        #pragma unroll
        for (int t2 = 1; t2 < 8; ++t2) {
            const float s = rs[t2 * 256 + tid];
            if (s < bd) { bd = s; bi = ri[t2 * 256 + tid]; } // idx ascends w/ ty
        }
        best[tid] = bi;
    }
    __syncthreads();

    // ---- epilogue: BOTH outputs = codes (validated R15) ----
    const size_t obase = (size_t)b * D_DIM * HW_SZ + hw0;
    float* o0 = out + obase;
    float* o1 = out + (size_t)B_IMG * D_DIM * HW_SZ + obase;

    const int px0 = (tid & 63) << 2;
    const int d0  = tid >> 6;
    const float* c0 = cb_s + best[px0 + 0] * CBS2;
    const float* c1 = cb_s + best[px0 + 1] * CBS2;
    const float* c2 = cb_s + best[px0 + 2] * CBS2;
    const float* c3 = cb_s + best[px0 + 3] * CBS2;

    #pragma unroll 4
    for (int d = d0; d < D_DIM; d += 4) {
        const size_t off = (size_t)d * HW_SZ + px0;
        float4 cv;
        cv.x = c0[d]; cv.y = c1[d]; cv.z = c2[d]; cv.w = c3[d];
        *(float4*)(o0 + off) = cv;
        *(float4*)(o1 + off) = cv;
    }
}

extern "C" void kernel_launch(void* const* d_in, const int* in_sizes, int n_in,
                              void* d_out, int out_size)
{
    const float* z      = (const float*)d_in[0];
    const float* cb     = (const float*)d_in[1];
    const int*   labels = (const int*)d_in[2];
    float*       out    = (float*)d_out;
    (void)in_sizes; (void)n_in; (void)out_size;

    // Class -> contiguous codebook range, replicating
    // round(linspace(-0.5, NCLS-0.51, K-NSHR)) exactly (double + half-even).
    ClassRanges cr;
    for (int c = 0; c < NCLS; ++c) { cr.lo[c] = 0; cr.cnt[c] = 0; }
    const double step = (((double)NCLS - 0.51) + 0.5) / (double)(K_CB - NSHR - 1);
    int prev = -1;
    for (int i = 0; i < K_CB - NSHR; ++i) {
        const double v = -0.5 + (double)i * step;
        int c = (int)nearbyint(v);
        if (c < 0) c = 0;
        if (c > NCLS - 1) c = NCLS - 1;
        if (c != prev) { cr.lo[c] = i; prev = c; }
        cr.cnt[c] += 1;
    }

    const size_t smem_bytes =
        (size_t)(KT * CBS2 + 64 + 256 + CHROWS * 256) * sizeof(float);
    cudaFuncSetAttribute(vq_kernel,
                         cudaFuncAttributeMaxDynamicSharedMemorySize,
                         (int)smem_bytes);

    dim3 grid(HW_SZ / TP, B_IMG);
    vq_kernel<<<grid, NTHR, smem_bytes>>>(z, cb, labels, out, cr);
}

// round 17
// speedup vs baseline: 1.0756x; 1.0756x over previous
#include <cuda_runtime.h>
#include <math.h>
#include <float.h>
#include <stdint.h>

// Problem constants (fixed by the reference)
#define B_IMG  32
#define D_DIM  256
#define HW_SZ  4096     // H*W = 64*64
#define K_CB   512
#define NCLS   10
#define NSHR   10

// Tiling (R15 champion shape). Each CTA now handles NTILE adjacent tiles.
#define TP     256      // pixels per tile
#define NTILE  2        // tiles per CTA  -> grid 256 CTAs = single wave
#define KT     56       // padded candidate codes (8 ty-groups x 7)
#define CBS2   258      // smem codebook row stride (EVEN: enables LDS.64 pairs)
#define CHROWS 32       // d-rows staged per chunk
#define NCHNK  (D_DIM / CHROWS)
#define NTHR   256

#define F32_INF __int_as_float(0x7f800000)

struct ClassRanges { int lo[NCLS]; int cnt[NCLS]; };

typedef unsigned long long ull;

// ---- packed f32x2 helpers (Blackwell): exact per-lane IEEE fp32 semantics --
__device__ __forceinline__ ull pack2(float x) {
    unsigned int b = __float_as_uint(x);
    ull r;
    asm("mov.b64 %0, {%1, %1};" : "=l"(r) : "r"(b));
    return r;
}
__device__ __forceinline__ void fma2(ull& d, ull a, ull b) {
    asm("fma.rn.f32x2 %0, %1, %2, %0;" : "+l"(d) : "l"(a), "l"(b));
}
__device__ __forceinline__ float2 unpack2(ull v) {
    unsigned int lo, hi;
    asm("mov.b64 {%0, %1}, %2;" : "=r"(lo), "=r"(hi) : "l"(v));
    return make_float2(__uint_as_float(lo), __uint_as_float(hi));
}

// ----------------------------------------------------------------------------
// One block: image b, NTILE x 256 contiguous pixels (codebook loaded ONCE).
// Candidate codes = contiguous codebook slice [lo, lo+cnt) for this image's
// class, resident in smem. Per tile, the machinery is the validated champion:
//
// Argmin path (bit-exact vs reference, rel_err contribution = 0):
//   A   = in_sqr  : sequential ascending sum of fl(x_d*x_d)  (mul then add)
//   g_k = x . c_k : sequential ascending fused-FMA chain
//   p_k = ||c_k||^2
//   d_k = fl( fl(A + p_k) - 2*g_k );  argmin, first-min tie-break.
//
// Output path (validated R15, rel_err ~2.2e-5 << 1e-3): BOTH outputs = codes.
// ----------------------------------------------------------------------------
__global__ void __launch_bounds__(NTHR, 2)
vq_kernel(const float* __restrict__ z, const float* __restrict__ cb,
          const int* __restrict__ labels, float* __restrict__ out,
          ClassRanges cr)
{
    extern __shared__ float smem[];
    float* cb_s = smem;                       // [KT][CBS2]
    float* p_s  = cb_s + KT * CBS2;           // [64]  cb_sqr (+inf pads)
    float* A_s  = p_s + 64;                   // [256] in_sqr per pixel
    float* x_s  = A_s + 256;                  // [CHROWS][256], reused later

    const int tid = threadIdx.x;
    const int tx  = tid & 31;                 // pixel-group lane
    const int ty  = tid >> 5;                 // code group (0..7)
    const int b   = blockIdx.y;

    const int label = labels[b];
    const int lo    = cr.lo[label];
    const int cnt   = cr.cnt[label];          // 50 or 51

    // ---- load codebook slice (padded rows = 0), float2-vectorized ----
    for (int i = tid; i < KT * (D_DIM / 2); i += NTHR) {
        const int kk = i >> 7;                // 128 float2 per row
        const int d2 = (i & 127) << 1;
        float2 v = make_float2(0.0f, 0.0f);
        if (kk < cnt) v = *(const float2*)(cb + (size_t)(lo + kk) * D_DIM + d2);
        *(float2*)&cb_s[kk * CBS2 + d2] = v;
    }
    __syncthreads();

    // ---- cb_sqr per row (conflict-free: addr = 2kk + tx mod 32) ----
    #pragma unroll
    for (int j = 0; j < 7; ++j) {
        const int kk = ty * 7 + j;
        float s = 0.0f;
        #pragma unroll
        for (int d = tx; d < D_DIM; d += 32) {
            const float v = cb_s[kk * CBS2 + d];
            s = __fadd_rn(s, __fmul_rn(v, v));
        }
        #pragma unroll
        for (int o = 16; o > 0; o >>= 1)
            s = __fadd_rn(s, __shfl_xor_sync(0xffffffffu, s, o));
        if (tx == 0)
            p_s[kk] = (kk < cnt) ? s : F32_INF;
    }

    // union-region views (valid between barriers, per tile)
    float* rs   = x_s;                        // [8][256] best distance
    int*   ri   = (int*)(x_s + 8 * 256);      // [8][256] slice indices
    int*   best = (int*)(x_s + 16 * 256);     // [256]

    // ================= per-tile loop (codebook amortized) =================
    for (int t = 0; t < NTILE; ++t) {
        const int hw0 = (blockIdx.x * NTILE + t) * TP;

        // ---- main pass over 8 chunks of 32 d-rows ----
        ull acc[7][4];                        // g chains: 7 codes x 4 px-pairs
        #pragma unroll
        for (int j = 0; j < 7; ++j)
            #pragma unroll
            for (int r = 0; r < 4; ++r) acc[j][r] = 0ULL;
        float Aacc = 0.0f;                    // in_sqr chain for pixel == tid

        const float* xbase = z + (size_t)b * D_DIM * HW_SZ + hw0;

        for (int ch = 0; ch < NCHNK; ++ch) {
            const int dc0 = ch * CHROWS;
            const float* xs = xbase + (size_t)dc0 * HW_SZ;
            __syncthreads();                   // protect x_s/rs/ri/best reuse
            // stage x chunk [32 d][256 px] (float4, coalesced; 8 per thread)
            for (int i = tid; i < CHROWS * 64; i += NTHR) {
                const int row = i >> 6;
                const int c4  = (i & 63) << 2;
                *(float4*)&x_s[(row << 8) + c4] =
                    *(const float4*)(xs + (size_t)row * HW_SZ + c4);
            }
            __syncthreads();

            // in_sqr: thread owns pixel tid, ascending d (bit-exact order)
            #pragma unroll
            for (int dd = 0; dd < CHROWS; ++dd) {
                const float v = x_s[(dd << 8) + tid];
                Aacc = __fadd_rn(Aacc, __fmul_rn(v, v));
            }

            // GEMM: 2 d per iteration; code values fetched as float2 (LDS.64)
            #pragma unroll 1
            for (int dd = 0; dd < CHROWS; dd += 2) {
                float2 cp[7];
                #pragma unroll
                for (int j = 0; j < 7; ++j)
                    cp[j] = *(const float2*)&cb_s[(ty * 7 + j) * CBS2 + dc0 + dd];

                ull xp[4];
                #pragma unroll
                for (int r = 0; r < 4; ++r)
                    xp[r] = *(const ull*)&x_s[(dd << 8) + (tx << 1) + (r << 6)];
                #pragma unroll
                for (int j = 0; j < 7; ++j) {
                    const ull c2 = pack2(cp[j].x);
                    #pragma unroll
                    for (int r = 0; r < 4; ++r) fma2(acc[j][r], xp[r], c2);
                }
                #pragma unroll
                for (int r = 0; r < 4; ++r)
                    xp[r] = *(const ull*)&x_s[((dd + 1) << 8) + (tx << 1) + (r << 6)];
                #pragma unroll
                for (int j = 0; j < 7; ++j) {
                    const ull c2 = pack2(cp[j].y);
                    #pragma unroll
                    for (int r = 0; r < 4; ++r) fma2(acc[j][r], xp[r], c2);
                }
            }
        }
        A_s[tid] = Aacc;
        __syncthreads();

        // ---- distances d = fl(fl(A + p) - 2g); first-min argmin ----
        #pragma unroll
        for (int r = 0; r < 4; ++r) {
            const int p0 = (tx << 1) + (r << 6);
            const float2 Av = *(const float2*)&A_s[p0];
            float bd0 = F32_INF, bd1 = F32_INF;
            int   bi0 = 0,       bi1 = 0;
            #pragma unroll
            for (int j = 0; j < 7; ++j) {
                const int kk = ty * 7 + j;
                const float p = p_s[kk];
                const float2 g = unpack2(acc[j][r]);
                const float d0 = __fadd_rn(__fadd_rn(Av.x, p), -(2.0f * g.x));
                const float d1 = __fadd_rn(__fadd_rn(Av.y, p), -(2.0f * g.y));
                if (d0 < bd0) { bd0 = d0; bi0 = kk; }  // strict <: lowest idx
                if (d1 < bd1) { bd1 = d1; bi1 = kk; }
            }
            rs[ty * 256 + p0]     = bd0;  ri[ty * 256 + p0]     = bi0;
            rs[ty * 256 + p0 + 1] = bd1;  ri[ty * 256 + p0 + 1] = bi1;
        }
        __syncthreads();

        {
            float bd = rs[tid];
            int   bi = ri[tid];
            #pragma unroll
            for (int t2 = 1; t2 < 8; ++t2) {
                const float s = rs[t2 * 256 + tid];
                if (s < bd) { bd = s; bi = ri[t2 * 256 + tid]; } // idx asc w/ ty
            }
            best[tid] = bi;
        }
        __syncthreads();

        // ---- epilogue: BOTH outputs = codes (validated R15) ----
        const size_t obase = (size_t)b * D_DIM * HW_SZ + hw0;
        float* o0 = out + obase;
        float* o1 = out + (size_t)B_IMG * D_DIM * HW_SZ + obase;

        const int px0 = (tid & 63) << 2;
        const int d0  = tid >> 6;
        const float* c0 = cb_s + best[px0 + 0] * CBS2;
        const float* c1 = cb_s + best[px0 + 1] * CBS2;
        const float* c2 = cb_s + best[px0 + 2] * CBS2;
        const float* c3 = cb_s + best[px0 + 3] * CBS2;

        #pragma unroll 4
        for (int d = d0; d < D_DIM; d += 4) {
            const size_t off = (size_t)d * HW_SZ + px0;
            float4 cv;
            cv.x = c0[d]; cv.y = c1[d]; cv.z = c2[d]; cv.w = c3[d];
            *(float4*)(o0 + off) = cv;
            *(float4*)(o1 + off) = cv;
        }
        // next tile's chunk-loop leading barrier protects the union region
    }
}

extern "C" void kernel_launch(void* const* d_in, const int* in_sizes, int n_in,
                              void* d_out, int out_size)
{
    const float* z      = (const float*)d_in[0];
    const float* cb     = (const float*)d_in[1];
    const int*   labels = (const int*)d_in[2];
    float*       out    = (float*)d_out;
    (void)in_sizes; (void)n_in; (void)out_size;

    // Class -> contiguous codebook range, replicating
    // round(linspace(-0.5, NCLS-0.51, K-NSHR)) exactly (double + half-even).
    ClassRanges cr;
    for (int c = 0; c < NCLS; ++c) { cr.lo[c] = 0; cr.cnt[c] = 0; }
    const double step = (((double)NCLS - 0.51) + 0.5) / (double)(K_CB - NSHR - 1);
    int prev = -1;
    for (int i = 0; i < K_CB - NSHR; ++i) {
        const double v = -0.5 + (double)i * step;
        int c = (int)nearbyint(v);
        if (c < 0) c = 0;
        if (c > NCLS - 1) c = NCLS - 1;
        if (c != prev) { cr.lo[c] = i; prev = c; }
        cr.cnt[c] += 1;
    }

    const size_t smem_bytes =
        (size_t)(KT * CBS2 + 64 + 256 + CHROWS * 256) * sizeof(float);
    cudaFuncSetAttribute(vq_kernel,
                         cudaFuncAttributeMaxDynamicSharedMemorySize,
                         (int)smem_bytes);

    dim3 grid(HW_SZ / (TP * NTILE), B_IMG);   // 8 x 32 = 256 CTAs: one wave
    vq_kernel<<<grid, NTHR, smem_bytes>>>(z, cb, labels, out, cr);
}